// round 2
// baseline (speedup 1.0000x reference)
#include <cuda_runtime.h>

// FeaturesLoss: 0.5 * ( sum_{same} D / zn1 + sum_{diff} max(0, margin - D) / zn2 )
// D[i,j] = max(0, sq_i + sq_j - 2 x_i . x_j),  symmetric -> upper triangle only.
// NOTE: labels are int32 (JAX default x64-disabled downcasts jnp.int64 -> int32).

#define BM 128
#define BN 128
#define BK 32
#define TM 8
#define TN 8
#define NTHREADS 256
#define MAX_N 8192

__device__ float g_sq[MAX_N];
__device__ double g_sum1;
__device__ double g_sum2;
__device__ unsigned long long g_cnt;

// ---------------------------------------------------------------------------
// Kernel A: per-row squared norms; block 0 thread 0 zeroes the accumulators.
// ---------------------------------------------------------------------------
__global__ void __launch_bounds__(128) sq_kernel(const float* __restrict__ X,
                                                 int n, int d) {
    if (blockIdx.x == 0 && threadIdx.x == 0) {
        g_sum1 = 0.0;
        g_sum2 = 0.0;
        g_cnt = 0ull;
    }
    int row = blockIdx.x;
    if (row >= n) return;
    const float* xr = X + (size_t)row * d;
    float s = 0.0f;
    for (int c = threadIdx.x; c < d; c += blockDim.x) {
        float v = xr[c];
        s = fmaf(v, v, s);
    }
#pragma unroll
    for (int o = 16; o > 0; o >>= 1)
        s += __shfl_down_sync(0xffffffffu, s, o);
    __shared__ float red[4];
    if ((threadIdx.x & 31) == 0) red[threadIdx.x >> 5] = s;
    __syncthreads();
    if (threadIdx.x == 0) {
        float t = red[0] + red[1] + red[2] + red[3];
        g_sq[row] = t;
    }
}

// ---------------------------------------------------------------------------
// Kernel B: upper-triangular tiled Gram + fused loss epilogue.
// ---------------------------------------------------------------------------
__global__ void __launch_bounds__(NTHREADS) pair_kernel(
    const float* __restrict__ X, const int* __restrict__ lab,
    const float* __restrict__ marginp, int n, int d, int nt) {
    __shared__ float As[BK][BM];
    __shared__ float Bs[BK][BN];
    __shared__ float sqA[BM];
    __shared__ float sqB[BN];
    __shared__ int labA[BM];
    __shared__ int labB[BN];

    // Decode linear block id -> (br, bc) with br <= bc (upper triangle).
    int b = blockIdx.x;
    int br = 0;
    int rowlen = nt;
    while (b >= rowlen) {
        b -= rowlen;
        rowlen--;
        br++;
    }
    int bc = br + b;

    const int rowBase = br * BM;
    const int colBase = bc * BN;
    const int tid = threadIdx.x;

    // Stage row norms + labels for this tile.
    for (int i = tid; i < BM; i += NTHREADS) {
        int gi = rowBase + i;
        int gj = colBase + i;
        sqA[i] = (gi < n) ? g_sq[gi] : 0.0f;
        sqB[i] = (gj < n) ? g_sq[gj] : 0.0f;
        labA[i] = (gi < n) ? lab[gi] : 0x7fffffff;
        labB[i] = (gj < n) ? lab[gj] : 0x7ffffffe;
    }

    float acc[TM][TN];
#pragma unroll
    for (int i = 0; i < TM; i++)
#pragma unroll
        for (int j = 0; j < TN; j++) acc[i][j] = 0.0f;

    const int tm = (tid >> 4) * TM;  // 0..120
    const int tn = (tid & 15) * TN;  // 0..120

    const int nChunks = (d + BK - 1) / BK;
    for (int kc = 0; kc < nChunks; kc++) {
        // Load 128x32 fp32 per operand: 4 float4 per thread per operand.
#pragma unroll
        for (int l = 0; l < 4; l++) {
            int flat = tid + l * NTHREADS;  // 0..1023 float4 slots
            int r = flat >> 3;              // row within tile, 0..127
            int k0 = (flat & 7) * 4;        // k offset within chunk, 0..28
            int kbase = kc * BK + k0;
            int gr = rowBase + r;
            int gc = colBase + r;
            float4 va = make_float4(0.f, 0.f, 0.f, 0.f);
            float4 vb = make_float4(0.f, 0.f, 0.f, 0.f);
            if (gr < n && kbase + 3 < d)
                va = *reinterpret_cast<const float4*>(X + (size_t)gr * d + kbase);
            if (gc < n && kbase + 3 < d)
                vb = *reinterpret_cast<const float4*>(X + (size_t)gc * d + kbase);
            As[k0 + 0][r] = va.x;
            As[k0 + 1][r] = va.y;
            As[k0 + 2][r] = va.z;
            As[k0 + 3][r] = va.w;
            Bs[k0 + 0][r] = vb.x;
            Bs[k0 + 1][r] = vb.y;
            Bs[k0 + 2][r] = vb.z;
            Bs[k0 + 3][r] = vb.w;
        }
        __syncthreads();
#pragma unroll
        for (int k = 0; k < BK; k++) {
            float a[TM], bfr[TN];
#pragma unroll
            for (int i = 0; i < TM; i++) a[i] = As[k][tm + i];
#pragma unroll
            for (int j = 0; j < TN; j++) bfr[j] = Bs[k][tn + j];
#pragma unroll
            for (int i = 0; i < TM; i++)
#pragma unroll
                for (int j = 0; j < TN; j++)
                    acc[i][j] = fmaf(a[i], bfr[j], acc[i][j]);
        }
        __syncthreads();
    }

    // Fused epilogue: per-pair loss terms with triangular weighting.
    const float margin = *marginp;
    const bool diag = (br == bc);
    float s1 = 0.0f, s2 = 0.0f;
    unsigned int cnt = 0;
#pragma unroll
    for (int i = 0; i < TM; i++) {
        int gi = rowBase + tm + i;
        float sqi = sqA[tm + i];
        int li = labA[tm + i];
#pragma unroll
        for (int j = 0; j < TN; j++) {
            int gj = colBase + tn + j;
            float w = 2.0f;
            if (diag) {
                if (gi > gj)
                    w = 0.0f;
                else if (gi == gj)
                    w = 1.0f;
            }
            if (gi < n && gj < n && w != 0.0f) {
                float D = sqi + sqB[tn + j] - 2.0f * acc[i][j];
                D = fmaxf(D, 0.0f);
                if (li == labB[tn + j]) {
                    s1 += w * D;
                    cnt += (unsigned int)w;
                } else {
                    s2 += w * fmaxf(0.0f, margin - D);
                }
            }
        }
    }

    // Block reduction -> global atomics (double for the scalar sums).
#pragma unroll
    for (int o = 16; o > 0; o >>= 1) {
        s1 += __shfl_down_sync(0xffffffffu, s1, o);
        s2 += __shfl_down_sync(0xffffffffu, s2, o);
        cnt += __shfl_down_sync(0xffffffffu, cnt, o);
    }
    __shared__ float r1[8], r2[8];
    __shared__ unsigned int rc[8];
    int wid = tid >> 5;
    if ((tid & 31) == 0) {
        r1[wid] = s1;
        r2[wid] = s2;
        rc[wid] = cnt;
    }
    __syncthreads();
    if (tid == 0) {
        double t1 = 0.0, t2 = 0.0;
        unsigned int tc = 0;
#pragma unroll
        for (int w = 0; w < 8; w++) {
            t1 += (double)r1[w];
            t2 += (double)r2[w];
            tc += rc[w];
        }
        atomicAdd(&g_sum1, t1);
        atomicAdd(&g_sum2, t2);
        atomicAdd(&g_cnt, (unsigned long long)tc);
    }
}

// ---------------------------------------------------------------------------
// Kernel C: final scalar combine.
// ---------------------------------------------------------------------------
__global__ void finalize_kernel(float* out, int n) {
    double zn1 = (double)g_cnt;
    double zn2 = (double)n * (double)n - zn1;
    double v = 0.5 * (g_sum1 / zn1 + g_sum2 / zn2);
    out[0] = (float)v;
}

extern "C" void kernel_launch(void* const* d_in, const int* in_sizes, int n_in,
                              void* d_out, int out_size) {
    const float* X = (const float*)d_in[0];
    const int* lab = (const int*)d_in[1];
    const float* marginp = (const float*)d_in[2];
    float* out = (float*)d_out;

    int n = in_sizes[1];
    int d = in_sizes[0] / n;

    sq_kernel<<<n, 128>>>(X, n, d);

    int nt = (n + BM - 1) / BM;
    int nb = nt * (nt + 1) / 2;
    pair_kernel<<<nb, NTHREADS>>>(X, lab, marginp, n, d, nt);

    finalize_kernel<<<1, 1>>>(out, n);
}

// round 4
// speedup vs baseline: 5.0184x; 5.0184x over previous
#include <cuda_runtime.h>
#include <cuda_bf16.h>
#include <cstdint>

// FeaturesLoss via legacy tensor-core mma.sync (bf16, m16n8k16) — compute_103-safe.
// Gram on upper triangle, 128x128 tiles, fused loss epilogue on register fragments.
// sq-norms exact fp32. n=4096 (mult of 128), d=512 (mult of 32) per setup_inputs.

#define BM 128
#define BN 128
#define BK 32
#define NTHREADS 256
#define MAXN 4096
#define MAXD 512
#define SSTR 40               // smem row stride in bf16 elems (80 B, LDSM conflict-free)

__device__ float g_sq[MAXN];
__device__ __align__(16) __nv_bfloat16 g_Xbf[MAXN * MAXD];
__device__ double g_sum1;
__device__ double g_sum2;
__device__ unsigned long long g_cnt;

__device__ __forceinline__ uint32_t smem_u32(const void* p) {
    uint32_t a;
    asm("{ .reg .u64 t; cvta.to.shared.u64 t, %1; cvt.u32.u64 %0, t; }"
        : "=r"(a) : "l"(p));
    return a;
}

#define CP_ASYNC16(dst_u32, src) \
    asm volatile("cp.async.cg.shared.global [%0], [%1], 16;" :: "r"(dst_u32), "l"(src))
#define CP_COMMIT() asm volatile("cp.async.commit_group;" ::: "memory")
#define CP_WAIT0()  asm volatile("cp.async.wait_group 0;" ::: "memory")

#define LDSM_X4(r0, r1, r2, r3, a)                                        \
    asm volatile("ldmatrix.sync.aligned.m8n8.x4.shared.b16 "              \
                 "{%0,%1,%2,%3}, [%4];"                                   \
                 : "=r"(r0), "=r"(r1), "=r"(r2), "=r"(r3) : "r"(a))

#define MMA16816(c, a0, a1, a2, a3, b0, b1)                               \
    asm volatile("mma.sync.aligned.m16n8k16.row.col.f32.bf16.bf16.f32 "   \
                 "{%0,%1,%2,%3}, {%4,%5,%6,%7}, {%8,%9}, {%0,%1,%2,%3};"  \
                 : "+f"((c)[0]), "+f"((c)[1]), "+f"((c)[2]), "+f"((c)[3]) \
                 : "r"(a0), "r"(a1), "r"(a2), "r"(a3), "r"(b0), "r"(b1))

// ---------------------------------------------------------------------------
// Kernel A: X -> bf16 scratch + exact fp32 row norms; zero accumulators.
// ---------------------------------------------------------------------------
__global__ void __launch_bounds__(256) convert_kernel(const float* __restrict__ X,
                                                      int n, int d) {
    if (blockIdx.x == 0 && threadIdx.x == 0) {
        g_sum1 = 0.0;
        g_sum2 = 0.0;
        g_cnt = 0ull;
    }
    int w = threadIdx.x >> 5, l = threadIdx.x & 31;
    int row = blockIdx.x * 8 + w;
    if (row >= n) return;
    const float4* src = reinterpret_cast<const float4*>(X + (size_t)row * d);
    __nv_bfloat162* dst = reinterpret_cast<__nv_bfloat162*>(g_Xbf + (size_t)row * d);
    float s = 0.0f;
    for (int c4 = l; c4 * 4 < d; c4 += 32) {
        float4 v = src[c4];
        s = fmaf(v.x, v.x, fmaf(v.y, v.y, fmaf(v.z, v.z, fmaf(v.w, v.w, s))));
        __nv_bfloat162 p0, p1;
        p0.x = __float2bfloat16(v.x);
        p0.y = __float2bfloat16(v.y);
        p1.x = __float2bfloat16(v.z);
        p1.y = __float2bfloat16(v.w);
        dst[c4 * 2 + 0] = p0;
        dst[c4 * 2 + 1] = p1;
    }
#pragma unroll
    for (int o = 16; o > 0; o >>= 1) s += __shfl_down_sync(0xffffffffu, s, o);
    if (l == 0) g_sq[row] = s;
}

// ---------------------------------------------------------------------------
// Kernel B: upper-triangular mma.sync Gram + fused loss epilogue.
// ---------------------------------------------------------------------------
__global__ void __launch_bounds__(NTHREADS, 2) pair_kernel(
    const int* __restrict__ lab, const float* __restrict__ marginp,
    int n, int d, int nt) {
    __shared__ __align__(1024) __nv_bfloat16 As[2][BM * SSTR];
    __shared__ __align__(1024) __nv_bfloat16 Bs[2][BN * SSTR];
    __shared__ float sqA[BM], sqB[BN];
    __shared__ int labA[BM], labB[BN];

    const int tid = threadIdx.x;
    const int wid = tid >> 5, lane = tid & 31;
    const int warpM = wid & 3;   // 4 warps over M: 32 rows each
    const int warpN = wid >> 2;  // 2 warps over N: 64 cols each

    // Decode linear block id -> (br, bc), br <= bc.
    int b = blockIdx.x, br = 0, rl = nt;
    while (b >= rl) {
        b -= rl;
        rl--;
        br++;
    }
    const int bc = br + b;
    const int rowBase = br * BM;
    const int colBase = bc * BN;

    for (int i = tid; i < BM; i += NTHREADS) {
        sqA[i] = g_sq[rowBase + i];
        sqB[i] = g_sq[colBase + i];
        labA[i] = lab[rowBase + i];
        labB[i] = lab[colBase + i];
    }

    const uint32_t aS0 = smem_u32(&As[0][0]);
    const uint32_t bS0 = smem_u32(&Bs[0][0]);
    const uint32_t stageA = (uint32_t)(BM * SSTR * 2);  // bytes per stage
    const __nv_bfloat16* __restrict__ Xb = g_Xbf;

    // Loader: chunk c (BK=32 cols) into stage c&1. 512 16B-pieces per operand.
    auto load_chunk = [&](int c) {
        const uint32_t aBase = aS0 + (uint32_t)(c & 1) * stageA;
        const uint32_t bBase = bS0 + (uint32_t)(c & 1) * stageA;
#pragma unroll
        for (int l = 0; l < 2; l++) {
            int flat = tid + l * NTHREADS;  // 0..511
            int r = flat >> 2;              // row 0..127
            int kc = flat & 3;              // 16B piece in row
            uint32_t off = (uint32_t)r * (SSTR * 2) + (uint32_t)kc * 16;
            const __nv_bfloat16* ga = Xb + (size_t)(rowBase + r) * d + c * BK + kc * 8;
            const __nv_bfloat16* gb = Xb + (size_t)(colBase + r) * d + c * BK + kc * 8;
            CP_ASYNC16(aBase + off, ga);
            CP_ASYNC16(bBase + off, gb);
        }
        CP_COMMIT();
    };

    float acc[2][8][4];
#pragma unroll
    for (int mt = 0; mt < 2; mt++)
#pragma unroll
        for (int ntile = 0; ntile < 8; ntile++)
#pragma unroll
            for (int e = 0; e < 4; e++) acc[mt][ntile][e] = 0.0f;

    // Per-lane ldmatrix x4 base offsets (rows lane&15, k-halves lane>>4).
    const uint32_t laneRow = (uint32_t)(lane & 15) * (SSTR * 2);
    const uint32_t laneK = (uint32_t)(lane >> 4) * 16;
    const uint32_t aLane = (uint32_t)(warpM * 32) * (SSTR * 2) + laneRow + laneK;
    const uint32_t bLane = (uint32_t)(warpN * 64) * (SSTR * 2) + laneRow + laneK;

    const int nChunks = d / BK;  // 16 for d=512
    load_chunk(0);

    for (int c = 0; c < nChunks; c++) {
        CP_WAIT0();
        __syncthreads();
        if (c + 1 < nChunks) load_chunk(c + 1);

        const uint32_t aBase = aS0 + (uint32_t)(c & 1) * stageA + aLane;
        const uint32_t bBase = bS0 + (uint32_t)(c & 1) * stageA + bLane;

        // A fragments: 2 m-tiles x 2 k16-steps.
        uint32_t a[2][2][4];
#pragma unroll
        for (int mt = 0; mt < 2; mt++)
#pragma unroll
            for (int ks = 0; ks < 2; ks++)
                LDSM_X4(a[mt][ks][0], a[mt][ks][1], a[mt][ks][2], a[mt][ks][3],
                        aBase + (uint32_t)mt * 16 * (SSTR * 2) + (uint32_t)ks * 32);

        // B: 4 n-tile pairs per k16-step; MMA immediately (low reg pressure).
#pragma unroll
        for (int ks = 0; ks < 2; ks++) {
#pragma unroll
            for (int ntp = 0; ntp < 4; ntp++) {
                uint32_t r0, r1, r2, r3;
                LDSM_X4(r0, r1, r2, r3,
                        bBase + (uint32_t)ntp * 16 * (SSTR * 2) + (uint32_t)ks * 32);
                // even n-tile fragment {r0,r2}, odd {r1,r3}
#pragma unroll
                for (int mt = 0; mt < 2; mt++) {
                    MMA16816(acc[mt][2 * ntp + 0], a[mt][ks][0], a[mt][ks][1],
                             a[mt][ks][2], a[mt][ks][3], r0, r2);
                    MMA16816(acc[mt][2 * ntp + 1], a[mt][ks][0], a[mt][ks][1],
                             a[mt][ks][2], a[mt][ks][3], r1, r3);
                }
            }
        }
        __syncthreads();
    }

    // Fused epilogue on C fragments.
    // c0: (row, col), c1: (row, col+1), c2: (row+8, col), c3: (row+8, col+1)
    const float margin = *marginp;
    const bool diag = (br == bc);
    float s1 = 0.0f, s2 = 0.0f;
    unsigned int cnt = 0;
#pragma unroll
    for (int mt = 0; mt < 2; mt++) {
        const int i0 = warpM * 32 + mt * 16 + (lane >> 2);
#pragma unroll
        for (int half = 0; half < 2; half++) {
            const int iloc = i0 + half * 8;
            const int gi = rowBase + iloc;
            const float sqi = sqA[iloc];
            const int li = labA[iloc];
#pragma unroll
            for (int ntile = 0; ntile < 8; ntile++) {
#pragma unroll
                for (int e = 0; e < 2; e++) {
                    const int jloc = warpN * 64 + ntile * 8 + (lane & 3) * 2 + e;
                    const int gj = colBase + jloc;
                    float w = 2.0f;
                    if (diag) w = (gi > gj) ? 0.0f : ((gi == gj) ? 1.0f : 2.0f);
                    if (w != 0.0f) {
                        float D = sqi + sqB[jloc] - 2.0f * acc[mt][ntile][half * 2 + e];
                        D = fmaxf(D, 0.0f);
                        if (li == labB[jloc]) {
                            s1 += w * D;
                            cnt += (unsigned int)w;
                        } else {
                            s2 += w * fmaxf(0.0f, margin - D);
                        }
                    }
                }
            }
        }
    }

    // Block reduction -> double atomics.
#pragma unroll
    for (int o = 16; o > 0; o >>= 1) {
        s1 += __shfl_down_sync(0xffffffffu, s1, o);
        s2 += __shfl_down_sync(0xffffffffu, s2, o);
        cnt += __shfl_down_sync(0xffffffffu, cnt, o);
    }
    __shared__ float r1[8], r2[8];
    __shared__ unsigned int rc[8];
    if ((lane) == 0) {
        r1[wid] = s1;
        r2[wid] = s2;
        rc[wid] = cnt;
    }
    __syncthreads();
    if (tid == 0) {
        double t1 = 0.0, t2 = 0.0;
        unsigned int tc = 0;
#pragma unroll
        for (int w = 0; w < 8; w++) {
            t1 += (double)r1[w];
            t2 += (double)r2[w];
            tc += rc[w];
        }
        atomicAdd(&g_sum1, t1);
        atomicAdd(&g_sum2, t2);
        atomicAdd(&g_cnt, (unsigned long long)tc);
    }
}

// ---------------------------------------------------------------------------
// Kernel C: final scalar combine.
// ---------------------------------------------------------------------------
__global__ void finalize_kernel(float* out, int n) {
    double zn1 = (double)g_cnt;
    double zn2 = (double)n * (double)n - zn1;
    out[0] = (float)(0.5 * (g_sum1 / zn1 + g_sum2 / zn2));
}

extern "C" void kernel_launch(void* const* d_in, const int* in_sizes, int n_in,
                              void* d_out, int out_size) {
    const float* X = (const float*)d_in[0];
    const int* lab = (const int*)d_in[1];
    const float* marginp = (const float*)d_in[2];
    float* out = (float*)d_out;

    int n = in_sizes[1];
    int d = in_sizes[0] / n;

    convert_kernel<<<(n + 7) / 8, 256>>>(X, n, d);

    int nt = (n + BM - 1) / BM;
    int nb = nt * (nt + 1) / 2;
    pair_kernel<<<nb, NTHREADS>>>(lab, marginp, n, d, nt);

    finalize_kernel<<<1, 1>>>(out, n);
}